// round 8
// baseline (speedup 1.0000x reference)
#include <cuda_runtime.h>
#include <cuda_bf16.h>
#include <cstdint>

// SVD recommender predict, cp.async-pipelined:
//   predict[b]  = clip(gm + bu[uid] + bi[iid] + dot(pu[uid], qi[iid]), 1, 5)
//   feat[b,:64] = pu[uid], feat[b,64:128] = qi[iid]
// d_out layout: [0:B) predict, [B : B+B*128) features row-major.
//
// Per block: 64 elements.
//   P1: stage 64 (uid,iid) pairs into smem (coalesced).
//   P2: 2048 cp.async.cg 16B ops pull all 64 feature rows (512B each) into
//       smem + cp.async.ca 4B bias prefetches. Register-free deep MLP.
//   P3: 4-lane groups compute dot from smem, write predict.
//   P4: linear smem -> gmem streaming copy of the feature rows (.cs).

#define N_FACTORS 64
#define BATCH     131072
#define BLOCK     256
#define EPB       64              // elements per block
#define ROW_B     256             // bytes per factor row (64 f32)
#define ELEM_B    512             // bytes per element (p row + q row)
#define STRIDE_B  560             // padded smem stride (512 + 48) -> conflict-light
#define NCHUNK    ((EPB * ELEM_B) / (BLOCK * 16))   // 8 chunks of 16B per thread

__device__ __forceinline__ void cp_async16(uint32_t dst_smem, const void* src) {
    asm volatile("cp.async.cg.shared.global [%0], [%1], 16;\n"
                 :: "r"(dst_smem), "l"(src));
}
__device__ __forceinline__ void cp_async4(uint32_t dst_smem, const void* src) {
    asm volatile("cp.async.ca.shared.global [%0], [%1], 4;\n"
                 :: "r"(dst_smem), "l"(src));
}

__global__ __launch_bounds__(BLOCK) void svd_predict_kernel(
    const int*   __restrict__ user_item,   // [BATCH*2]
    const char*  __restrict__ pu,          // byte view, rows of 256B
    const char*  __restrict__ qi,
    const float* __restrict__ bu,
    const float* __restrict__ bi,
    const float* __restrict__ gmean,
    float*       __restrict__ out_pred,    // [BATCH]
    char*        __restrict__ out_feat)    // [BATCH*512] bytes
{
    __shared__ int   s_idx[EPB * 2];             // (uid,iid) interleaved
    __shared__ float s_bu[EPB];
    __shared__ float s_bi[EPB];
    __shared__ __align__(16) char s_data[EPB * STRIDE_B];

    const int tid   = threadIdx.x;
    const int eb    = blockIdx.x * EPB;          // first element of this block

    // ── P1: stage indices (128 ints = 512B, coalesced) ─────────────────────
    if (tid < EPB * 2)
        s_idx[tid] = user_item[eb * 2 + tid];
    __syncthreads();

    // ── P2: async gather of all rows + biases into smem ────────────────────
    const uint32_t s_data_base = (uint32_t)__cvta_generic_to_shared(s_data);
    #pragma unroll
    for (int c = 0; c < NCHUNK; c++) {
        const int id  = tid + BLOCK * c;         // 0..2047
        const int e   = id >> 5;                 // element (32 chunks each)
        const int off = (id & 31) << 4;          // byte offset 0..496
        const int uid = s_idx[e * 2 + 0];
        const int iid = s_idx[e * 2 + 1];
        const char* src = (off < ROW_B)
            ? pu + (size_t)uid * ROW_B + off
            : qi + (size_t)iid * ROW_B + (off - ROW_B);
        cp_async16(s_data_base + e * STRIDE_B + off, src);
    }
    {
        const uint32_t s_bu_base = (uint32_t)__cvta_generic_to_shared(s_bu);
        const uint32_t s_bi_base = (uint32_t)__cvta_generic_to_shared(s_bi);
        if (tid < EPB) {
            cp_async4(s_bu_base + tid * 4, bu + s_idx[tid * 2 + 0]);
        } else if (tid < EPB * 2) {
            const int e = tid - EPB;
            cp_async4(s_bi_base + e * 4, bi + s_idx[e * 2 + 1]);
        }
    }
    asm volatile("cp.async.commit_group;\n");
    asm volatile("cp.async.wait_group 0;\n" ::: "memory");
    __syncthreads();

    // ── P3: dot product per 4-lane group, write predict ────────────────────
    {
        const int g    = tid >> 2;               // element within block
        const int lane = tid & 3;
        const char* base = s_data + g * STRIDE_B;
        float dot = 0.0f;
        #pragma unroll
        for (int j = 0; j < 4; j++) {
            const float4 p = *(const float4*)(base + (lane + 4 * j) * 16);
            const float4 q = *(const float4*)(base + ROW_B + (lane + 4 * j) * 16);
            dot += p.x * q.x + p.y * q.y + p.z * q.z + p.w * q.w;
        }
        dot += __shfl_xor_sync(0xffffffffu, dot, 2);
        dot += __shfl_xor_sync(0xffffffffu, dot, 1);
        if (lane == 0) {
            float pr = gmean[0] + s_bu[g] + s_bi[g] + dot;
            pr = fminf(fmaxf(pr, 1.0f), 5.0f);
            __stcs(out_pred + eb + g, pr);
        }
    }

    // ── P4: linear smem -> gmem feature stream (perfectly coalesced) ───────
    {
        char* gbase = out_feat + (size_t)eb * ELEM_B;
        #pragma unroll
        for (int c = 0; c < NCHUNK; c++) {
            const int id  = tid + BLOCK * c;
            const int e   = id >> 5;
            const int off = (id & 31) << 4;
            const float4 v = *(const float4*)(s_data + e * STRIDE_B + off);
            __stcs((float4*)(gbase + e * ELEM_B + off), v);
        }
    }
}

extern "C" void kernel_launch(void* const* d_in, const int* in_sizes, int n_in,
                              void* d_out, int out_size)
{
    const int*   user_item = (const int*)  d_in[0];
    const char*  pu        = (const char*) d_in[1];
    const char*  qi        = (const char*) d_in[2];
    const float* bu        = (const float*)d_in[3];
    const float* bi        = (const float*)d_in[4];
    const float* gmean     = (const float*)d_in[5];

    float* out_pred = (float*)d_out;
    char*  out_feat = (char*)((float*)d_out + BATCH);

    const int blocks = BATCH / EPB;   // 2048
    svd_predict_kernel<<<blocks, BLOCK>>>(user_item, pu, qi, bu, bi, gmean,
                                          out_pred, out_feat);
}